// round 9
// baseline (speedup 1.0000x reference)
#include <cuda_runtime.h>
#include <math.h>

// Problem constants
// q: [128,128,128]  k,v: [128,32,32]  conv_w: [128,128,3,3]
// normq_w/normk_w: [128]  qproj_w/kproj_w: [128,128]  qproj_b/kproj_b: [128]
// out: [128,128,128] fp32

#define NPIX_Q 16384   // 128*128
#define NPIX_K 1024    // 32*32
#define EPSF 1.1920929e-07f

// ---------------- scratch (device globals; no allocation allowed) ----------
__device__ float g_qc[128 * NPIX_Q];   // conv output
__device__ float g_qp[128 * NPIX_Q];   // projected q
__device__ float g_kp[128 * NPIX_K];   // projected k
__device__ float g_qscale[NPIX_Q];
__device__ float g_kscale[NPIX_K];

// ---------------- packed f32x2 helpers (sm_100+ PTX) -----------------------
__device__ __forceinline__ unsigned long long pack2(float lo, float hi) {
    unsigned long long r;
    asm("mov.b64 %0, {%1, %2};" : "=l"(r) : "f"(lo), "f"(hi));
    return r;
}
__device__ __forceinline__ void unpack2(float& lo, float& hi,
                                        unsigned long long v) {
    asm("mov.b64 {%0, %1}, %2;" : "=f"(lo), "=f"(hi) : "l"(v));
}
__device__ __forceinline__ unsigned long long ffma2(unsigned long long a,
                                                    unsigned long long b,
                                                    unsigned long long c) {
    unsigned long long d;
    asm("fma.rn.f32x2 %0, %1, %2, %3;" : "=l"(d) : "l"(a), "l"(b), "l"(c));
    return d;
}

// ======================= 3x3 conv, pad=1, no bias ==========================
// CTA: 256 threads -> tile of 32 co x 16y x 8x. grid (16,8,4).
// Thread = (co, ry) computes output rows 2ry and 2ry+1 (8 px each) as packed
// f32x2 pairs. Input rows are shared between the two output rows: sin_ row
// (2ry+d) feeds out-row0 at ky=d (d<=2) and out-row1 at ky=d-1 (d>=1), so
// each row is packed once and applied twice. Bit-identical to scalar fp32.
__global__ void __launch_bounds__(256) conv3x3_k(const float* __restrict__ x,
                                                 const float* __restrict__ w) {
    __shared__ float sin_[16][18][12];   // ci x (16+2)y x padded x
    __shared__ float sw[32 * 16 * 12];   // co x ci x 12 (9 used, float4-aligned)
    const int t = threadIdx.x;
    const int co_l = t >> 3, ry = t & 7;
    const int x0 = blockIdx.x * 8, y0 = blockIdx.y * 16, co0 = blockIdx.z * 32;

    unsigned long long acc2[8];          // [half][pair]: 0..3 row 2ry, 4..7 row 2ry+1
#pragma unroll
    for (int i = 0; i < 8; i++) acc2[i] = 0ull;

    for (int cc = 0; cc < 128; cc += 16) {
        __syncthreads();   // protect smem from previous iteration's readers
        // input patch 16 x 18 x 10 (zero padded)
        for (int e = t; e < 2880; e += 256) {
            int ci = e / 180, r = e % 180, iy = r / 10, ix = r % 10;
            int gy = y0 + iy - 1, gx = x0 + ix - 1;
            float v = 0.f;
            if ((unsigned)gy < 128u && (unsigned)gx < 128u)
                v = x[(cc + ci) * 16384 + gy * 128 + gx];
            sin_[ci][iy][ix] = v;
        }
        // weights: 32co x 16ci x 9 -> padded stride 12
#pragma unroll
        for (int e = t; e < 4608; e += 256) {
            int co = e / 144, r = e % 144;
            int ci = r / 9, kk = r - ci * 9;
            sw[co * 192 + ci * 12 + kk] = w[(co0 + co) * 1152 + cc * 9 + r];
        }
        __syncthreads();
        const float* wbase = &sw[co_l * 192];
#pragma unroll
        for (int ci = 0; ci < 16; ci++) {
            float4 wa = *(const float4*)(wbase + ci * 12);
            float4 wb = *(const float4*)(wbase + ci * 12 + 4);
            float wcs = wbase[ci * 12 + 8];
            unsigned long long wd[9] = {
                pack2(wa.x, wa.x), pack2(wa.y, wa.y), pack2(wa.z, wa.z),
                pack2(wa.w, wa.w), pack2(wb.x, wb.x), pack2(wb.y, wb.y),
                pack2(wb.z, wb.z), pack2(wb.w, wb.w), pack2(wcs, wcs)};
#pragma unroll
            for (int d = 0; d < 4; d++) {
                const float* row = &sin_[ci][2 * ry + d][0];
                float4 a = *(const float4*)(row);
                float4 b = *(const float4*)(row + 4);
                float2 c2 = *(const float2*)(row + 8);
                // ev[j] = (r[2j], r[2j+1]);  od[j] = (r[2j+1], r[2j+2])
                unsigned long long ev[5] = {
                    pack2(a.x, a.y), pack2(a.z, a.w), pack2(b.x, b.y),
                    pack2(b.z, b.w), pack2(c2.x, c2.y)};
                unsigned long long od[4] = {
                    pack2(a.y, a.z), pack2(a.w, b.x),
                    pack2(b.y, b.z), pack2(b.w, c2.x)};
                if (d < 3) {                    // out-row 2ry, ky = d
                    unsigned long long w0 = wd[d * 3 + 0];
                    unsigned long long w1 = wd[d * 3 + 1];
                    unsigned long long w2 = wd[d * 3 + 2];
#pragma unroll
                    for (int p = 0; p < 4; p++) {
                        acc2[p] = ffma2(w0, ev[p], acc2[p]);
                        acc2[p] = ffma2(w1, od[p], acc2[p]);
                        acc2[p] = ffma2(w2, ev[p + 1], acc2[p]);
                    }
                }
                if (d >= 1) {                   // out-row 2ry+1, ky = d-1
                    unsigned long long w0 = wd[(d - 1) * 3 + 0];
                    unsigned long long w1 = wd[(d - 1) * 3 + 1];
                    unsigned long long w2 = wd[(d - 1) * 3 + 2];
#pragma unroll
                    for (int p = 0; p < 4; p++) {
                        acc2[4 + p] = ffma2(w0, ev[p], acc2[4 + p]);
                        acc2[4 + p] = ffma2(w1, od[p], acc2[4 + p]);
                        acc2[4 + p] = ffma2(w2, ev[p + 1], acc2[4 + p]);
                    }
                }
            }
        }
    }
#pragma unroll
    for (int half = 0; half < 2; half++) {
        float o[8];
#pragma unroll
        for (int p = 0; p < 4; p++)
            unpack2(o[2 * p], o[2 * p + 1], acc2[half * 4 + p]);
        float* op = &g_qc[(co0 + co_l) * 16384 + (y0 + 2 * ry + half) * 128 + x0];
        *(float4*)op = make_float4(o[0], o[1], o[2], o[3]);
        *(float4*)(op + 4) = make_float4(o[4], o[5], o[6], o[7]);
    }
}

// ================= per-pixel RMS scale: rsqrt(mean_c x^2 + eps) ============
__global__ void rms_scale_k(const float* __restrict__ x, float* __restrict__ s,
                            int P) {
    int p = blockIdx.x * 256 + threadIdx.x;   // P multiple of 256
    float acc = 0.f;
#pragma unroll 8
    for (int c = 0; c < 128; c++) {
        float v = x[c * P + p];
        acc = fmaf(v, v, acc);
    }
    s[p] = rsqrtf(acc * (1.f / 128.f) + EPSF);
}

// ========== fused rmsnorm + 1x1 projection:  y = scale_p*(W.nw)@x + b ======
// CTA 256 threads: 128 o x 64 p tile; thread = (o-block of 32, one p).
__global__ void __launch_bounds__(256) proj_k(const float* __restrict__ x,
                                              const float* __restrict__ W,
                                              const float* __restrict__ bias,
                                              const float* __restrict__ nw,
                                              const float* __restrict__ scale,
                                              float* __restrict__ y, int P) {
    extern __shared__ float swm[];   // [128][128]  W[o][c]*nw[c]
    const int t = threadIdx.x;
    const int tx = t & 63, ty = t >> 6;
    const int p = blockIdx.x * 64 + tx;
#pragma unroll
    for (int e = t; e < 16384; e += 256) {
        int c = e & 127;
        swm[e] = W[e] * nw[c];
    }
    __syncthreads();

    unsigned long long acc2[32];
#pragma unroll
    for (int r = 0; r < 32; r++) acc2[r] = 0ull;
    const int o0 = ty * 32;
    for (int c4 = 0; c4 < 128; c4 += 4) {
        float x0 = x[(c4 + 0) * P + p];
        float x1 = x[(c4 + 1) * P + p];
        float x2 = x[(c4 + 2) * P + p];
        float x3 = x[(c4 + 3) * P + p];
        unsigned long long xp01 = pack2(x0, x1);
        unsigned long long xp23 = pack2(x2, x3);
#pragma unroll
        for (int r = 0; r < 32; r++) {
            const unsigned long long* wp =
                (const unsigned long long*)&swm[(o0 + r) * 128 + c4];
            acc2[r] = ffma2(wp[0], xp01, acc2[r]);
            acc2[r] = ffma2(wp[1], xp23, acc2[r]);
        }
    }
    float sp = scale[p];
#pragma unroll
    for (int r = 0; r < 32; r++) {
        float lo, hi;
        unpack2(lo, hi, acc2[r]);
        y[(o0 + r) * P + p] = fmaf(lo + hi, sp, __ldg(&bias[o0 + r]));
    }
}

// ======================= NATTEN attention ==================================
// Dilation 4 == upsample factor 4  =>  each query (i,j) attends to the
// contiguous 7x7 window starting at s0(i)=clamp((i-12)>>2,0,25) on the 32x32
// k-grid; constant across each 4x4 query tile. CTA = 8x8 queries = 2x2 tiles
// sharing one 8x8 key union (per-tile offset delta in {0,1}).
// 512 thr, 16 warps; warp = 4 queries of one tile (K/V smem reads amortized
// 4x across queries). grid (16,16).
__global__ void __launch_bounds__(512) natten_k(const float* __restrict__ vin,
                                                float* __restrict__ out) {
    extern __shared__ float sm[];
    float* sq = sm;                      // 64 x 128 (reused as output staging)
    float* sk = sm + 8192;               // 64 keys x 132
    float* sv = sk + 64 * 132;           // 64 keys x 132
    float* sattn = sv + 64 * 132;        // 64 x 52

    const int t = threadIdx.x;
    const int w = t >> 5, lane = t & 31;
    const int j0 = blockIdx.x * 8, i0 = blockIdx.y * 8;

    int s0ai = (i0 - 12) >> 2; s0ai = max(0, min(25, s0ai));
    int s0bi = (i0 - 8) >> 2;  s0bi = max(0, min(25, s0bi));
    int s0aj = (j0 - 12) >> 2; s0aj = max(0, min(25, s0aj));
    int s0bj = (j0 - 8) >> 2;  s0bj = max(0, min(25, s0bj));

    // ---- stage q: 8x8 queries, sq[g][c] with g = qi*8 + qj ----
#pragma unroll
    for (int e = t; e < 2048; e += 512) {
        int c = e >> 4, rest = e & 15, qi = rest >> 1, half = rest & 1;
        float4 v4 = *(const float4*)&g_qp[c * 16384 + (i0 + qi) * 128 + j0 + 4 * half];
        int g0 = qi * 8 + 4 * half;
        sq[(g0 + 0) * 128 + c] = v4.x;
        sq[(g0 + 1) * 128 + c] = v4.y;
        sq[(g0 + 2) * 128 + c] = v4.z;
        sq[(g0 + 3) * 128 + c] = v4.w;
    }
    // ---- stage 8x8 key union (rows/cols clamped; clamped slots unread) ----
#pragma unroll
    for (int e = t; e < 8192; e += 512) {
        int c = e >> 6, kidx = e & 63, kr = kidx >> 3, kc = kidx & 7;
        int gr = min(s0ai + kr, 31), gc = min(s0aj + kc, 31);
        int ga = c * 1024 + gr * 32 + gc;
        sk[kidx * 132 + c] = g_kp[ga];
        sv[kidx * 132 + c] = vin[ga];
    }
    __syncthreads();

    // ---- warp -> tile T (0..3), 4 queries (one row of 4 within the tile) --
    const int T = w >> 2, ws = w & 3;
    const int di = (T >> 1) ? (s0bi - s0ai) : 0;
    const int dj = (T & 1) ? (s0bj - s0aj) : 0;
    const int gbase = (((T >> 1) << 2) + ws) * 8 + ((T & 1) << 2);

    const bool has2 = lane < 17;
    const int kk0 = lane, kk1 = has2 ? lane + 32 : lane;
    const float* k0p = &sk[((di + kk0 / 7) * 8 + dj + kk0 % 7) * 132];
    const float* k1p = &sk[((di + kk1 / 7) * 8 + dj + kk1 % 7) * 132];
    const float* qbase = &sq[gbase * 128];

    float attn0[4] = {0.f, 0.f, 0.f, 0.f}, attn1[4] = {0.f, 0.f, 0.f, 0.f};
#pragma unroll
    for (int h = 0; h < 4; h++) {
        float l0[4] = {0.f, 0.f, 0.f, 0.f}, l1[4] = {0.f, 0.f, 0.f, 0.f};
#pragma unroll
        for (int d4 = 0; d4 < 8; d4++) {
            int off = h * 32 + d4 * 4;
            float4 ka = *(const float4*)&k0p[off];
            float4 kb = *(const float4*)&k1p[off];
#pragma unroll
            for (int qq = 0; qq < 4; qq++) {
                float4 qd = *(const float4*)&qbase[qq * 128 + off];
                l0[qq] += qd.x * ka.x + qd.y * ka.y + qd.z * ka.z + qd.w * ka.w;
                l1[qq] += qd.x * kb.x + qd.y * kb.y + qd.z * kb.z + qd.w * kb.w;
            }
        }
        const float SC = 0.17677669529663687f;   // 32^-0.5
#pragma unroll
        for (int qq = 0; qq < 4; qq++) {
            float a0 = l0[qq] * SC, a1 = l1[qq] * SC;
            float mx = has2 ? fmaxf(a0, a1) : a0;
#pragma unroll
            for (int o = 16; o; o >>= 1)
                mx = fmaxf(mx, __shfl_xor_sync(0xffffffffu, mx, o));
            float e0 = __expf(a0 - mx);
            float e1 = has2 ? __expf(a1 - mx) : 0.f;
            float s = e0 + e1;
#pragma unroll
            for (int o = 16; o; o >>= 1)
                s += __shfl_xor_sync(0xffffffffu, s, o);
            float inv = 0.25f / s;               // fold mean over 4 heads
            attn0[qq] = fmaf(e0, inv, attn0[qq]);
            attn1[qq] = fmaf(e1, inv, attn1[qq]);
        }
    }
#pragma unroll
    for (int qq = 0; qq < 4; qq++) {
        sattn[(gbase + qq) * 52 + lane] = attn0[qq];
        if (has2) sattn[(gbase + qq) * 52 + lane + 32] = attn1[qq];
    }
    __syncwarp();

    // ---- AV: lane owns channels 4l..4l+3; V loaded once per key, used by
    // all 4 queries of the warp ----
    float4 a4[4];
#pragma unroll
    for (int qq = 0; qq < 4; qq++) a4[qq] = make_float4(0.f, 0.f, 0.f, 0.f);
#pragma unroll
    for (int m = 0; m < 7; m++) {
#pragma unroll
        for (int n = 0; n < 7; n++) {
            float4 vv = *(const float4*)&sv[((di + m) * 8 + dj + n) * 132 + 4 * lane];
            int kk = m * 7 + n;
#pragma unroll
            for (int qq = 0; qq < 4; qq++) {
                float aw = sattn[(gbase + qq) * 52 + kk];
                a4[qq].x = fmaf(aw, vv.x, a4[qq].x);
                a4[qq].y = fmaf(aw, vv.y, a4[qq].y);
                a4[qq].z = fmaf(aw, vv.z, a4[qq].z);
                a4[qq].w = fmaf(aw, vv.w, a4[qq].w);
            }
        }
    }
    // stage into sq (warp-private rows; no cross-warp hazard before barrier)
#pragma unroll
    for (int qq = 0; qq < 4; qq++)
        *(float4*)&sq[(gbase + qq) * 128 + 4 * lane] = a4[qq];
    __syncthreads();

    // ---- coalesced store: float4 along x per (c, qi, half) ----
#pragma unroll
    for (int e = t; e < 2048; e += 512) {
        int c = e >> 4, rest = e & 15, qi = rest >> 1, half = rest & 1;
        int g0 = qi * 8 + 4 * half;
        float4 o4 = make_float4(sq[(g0 + 0) * 128 + c], sq[(g0 + 1) * 128 + c],
                                sq[(g0 + 2) * 128 + c], sq[(g0 + 3) * 128 + c]);
        *(float4*)&out[c * 16384 + (i0 + qi) * 128 + j0 + 4 * half] = o4;
    }
}

// ============================== launch =====================================
extern "C" void kernel_launch(void* const* d_in, const int* in_sizes, int n_in,
                              void* d_out, int out_size) {
    const float* q  = (const float*)d_in[0];
    const float* k  = (const float*)d_in[1];
    const float* v  = (const float*)d_in[2];
    const float* cw = (const float*)d_in[3];
    const float* nq = (const float*)d_in[4];
    const float* nk = (const float*)d_in[5];
    const float* qw = (const float*)d_in[6];
    const float* qb = (const float*)d_in[7];
    const float* kw = (const float*)d_in[8];
    const float* kb = (const float*)d_in[9];
    float* out = (float*)d_out;

    // scratch addresses (cudaGetSymbolAddress is immediate, capture-safe)
    float *p_qc, *p_qp, *p_kp, *p_qs, *p_ks;
    cudaGetSymbolAddress((void**)&p_qc, g_qc);
    cudaGetSymbolAddress((void**)&p_qp, g_qp);
    cudaGetSymbolAddress((void**)&p_kp, g_kp);
    cudaGetSymbolAddress((void**)&p_qs, g_qscale);
    cudaGetSymbolAddress((void**)&p_ks, g_kscale);

    // opt-in smem limits (idempotent; deterministic)
    cudaFuncSetAttribute(proj_k, cudaFuncAttributeMaxDynamicSharedMemorySize,
                         128 * 128 * 4);
    const int natten_smem = (8192 + 2 * 64 * 132 + 64 * 52) * 4;  // 113664 B
    cudaFuncSetAttribute(natten_k, cudaFuncAttributeMaxDynamicSharedMemorySize,
                         natten_smem);

    // 1) 3x3 conv on q
    conv3x3_k<<<dim3(16, 8, 4), 256>>>(q, cw);
    // 2) RMS scales
    rms_scale_k<<<NPIX_Q / 256, 256>>>(p_qc, p_qs, NPIX_Q);
    rms_scale_k<<<NPIX_K / 256, 256>>>(k, p_ks, NPIX_K);
    // 3) fused rmsnorm + 1x1 projections
    proj_k<<<NPIX_Q / 64, 256, 128 * 128 * 4>>>(p_qc, qw, qb, nq, p_qs, p_qp,
                                                NPIX_Q);
    proj_k<<<NPIX_K / 64, 256, 128 * 128 * 4>>>(k, kw, kb, nk, p_ks, p_kp,
                                                NPIX_K);
    // 4) neighborhood attention + head-mean + AV
    natten_k<<<dim3(16, 16), 512, natten_smem>>>(v, out);
}

// round 12
// speedup vs baseline: 1.1882x; 1.1882x over previous
#include <cuda_runtime.h>
#include <math.h>

// Problem constants
// q: [128,128,128]  k,v: [128,32,32]  conv_w: [128,128,3,3]
// normq_w/normk_w: [128]  qproj_w/kproj_w: [128,128]  qproj_b/kproj_b: [128]
// out: [128,128,128] fp32

#define NPIX_Q 16384   // 128*128
#define NPIX_K 1024    // 32*32
#define EPSF 1.1920929e-07f

// ---------------- scratch (device globals; no allocation allowed) ----------
__device__ float g_qc[128 * NPIX_Q];   // conv output
__device__ float g_qp[128 * NPIX_Q];   // projected q
__device__ float g_kp[128 * NPIX_K];   // projected k

// ======================= 3x3 conv, pad=1, no bias ==========================
// CTA: 256 threads -> tile of 32 co x 8y x 8x. grid (16,16,4).
// Scalar fp32 (f32x2 experiment reverted: measured 128-reg/25%-occ collapse).
// launch_bounds(256,4) caps regs at 64 -> 4 CTAs/SM for latency hiding.
__global__ void __launch_bounds__(256, 4) conv3x3_k(const float* __restrict__ x,
                                                    const float* __restrict__ w) {
    __shared__ float sin_[16][10][12];   // ci x (8+2)y x padded x
    __shared__ float sw[32 * 16 * 12];   // co x ci x 12 (9 used, float4-aligned)
    const int t = threadIdx.x;
    const int co_l = t >> 3, ry = t & 7;
    const int x0 = blockIdx.x * 8, y0 = blockIdx.y * 8, co0 = blockIdx.z * 32;

    float acc[8];
#pragma unroll
    for (int i = 0; i < 8; i++) acc[i] = 0.f;

    for (int cc = 0; cc < 128; cc += 16) {
        __syncthreads();   // protect smem from previous iteration's readers
        // input patch 16 x 10 x 10 (zero padded)
#pragma unroll
        for (int e = t; e < 1600; e += 256) {
            int ci = e / 100, r = e % 100, iy = r / 10, ix = r % 10;
            int gy = y0 + iy - 1, gx = x0 + ix - 1;
            float v = 0.f;
            if ((unsigned)gy < 128u && (unsigned)gx < 128u)
                v = x[(cc + ci) * 16384 + gy * 128 + gx];
            sin_[ci][iy][ix] = v;
        }
        // weights: 32co x 16ci x 9 -> padded stride 12
#pragma unroll
        for (int e = t; e < 4608; e += 256) {
            int co = e / 144, r = e % 144;
            int ci = r / 9, kk = r - ci * 9;
            sw[co * 192 + ci * 12 + kk] = w[(co0 + co) * 1152 + cc * 9 + r];
        }
        __syncthreads();
        const float* wbase = &sw[co_l * 192];
#pragma unroll
        for (int ci = 0; ci < 16; ci++) {
            float4 wa = *(const float4*)(wbase + ci * 12);
            float4 wb = *(const float4*)(wbase + ci * 12 + 4);
            float wcs = wbase[ci * 12 + 8];
            float wk[9] = {wa.x, wa.y, wa.z, wa.w, wb.x, wb.y, wb.z, wb.w, wcs};
#pragma unroll
            for (int ky = 0; ky < 3; ky++) {
                const float* row = &sin_[ci][ry + ky][0];
                float4 a = *(const float4*)(row);
                float4 b = *(const float4*)(row + 4);
                float2 c2 = *(const float2*)(row + 8);
                float r10[10] = {a.x, a.y, a.z, a.w, b.x, b.y, b.z, b.w, c2.x, c2.y};
#pragma unroll
                for (int kx = 0; kx < 3; kx++) {
                    float wv = wk[ky * 3 + kx];
#pragma unroll
                    for (int xx = 0; xx < 8; xx++)
                        acc[xx] = fmaf(wv, r10[xx + kx], acc[xx]);
                }
            }
        }
    }
    float* op = &g_qc[(co0 + co_l) * 16384 + (y0 + ry) * 128 + x0];
    *(float4*)op = make_float4(acc[0], acc[1], acc[2], acc[3]);
    *(float4*)(op + 4) = make_float4(acc[4], acc[5], acc[6], acc[7]);
}

// ===== fused rmsnorm + 1x1 projection:  y = rms_p*(W.nw)@x + b =============
// The per-pixel RMS scale is computed INLINE (each thread already reads all
// 128 channels of its pixel), deleting the separate rms pass + launches.
// ssq accumulates in the same sequential c-order as before (bit-identical).
// Thread owns 16 outputs (acc[16] ~40 regs), o-dim split across blockIdx.y
// (64 o per CTA, 32 KB W-slice in smem). CTA 256 thr = 64 p x 4 o-blocks.
__global__ void __launch_bounds__(256, 4) proj_k(const float* __restrict__ x,
                                                 const float* __restrict__ W,
                                                 const float* __restrict__ bias,
                                                 const float* __restrict__ nw,
                                                 float* __restrict__ y, int P) {
    extern __shared__ float swm[];   // [64][128]  W[o_base+r][c]*nw[c]
    const int t = threadIdx.x;
    const int tx = t & 63, ty = t >> 6;
    const int p = blockIdx.x * 64 + tx;
    const int o_base = blockIdx.y * 64;
#pragma unroll
    for (int e = t; e < 8192; e += 256) {
        int r = e >> 7, c = e & 127;
        swm[e] = W[(o_base + r) * 128 + c] * nw[c];
    }
    __syncthreads();

    float acc[16];
#pragma unroll
    for (int r = 0; r < 16; r++) acc[r] = 0.f;
    float ssq = 0.f;
    const int o0 = ty * 16;
    for (int c4 = 0; c4 < 128; c4 += 4) {
        float x0 = x[(c4 + 0) * P + p];
        float x1 = x[(c4 + 1) * P + p];
        float x2 = x[(c4 + 2) * P + p];
        float x3 = x[(c4 + 3) * P + p];
        ssq = fmaf(x0, x0, ssq);
        ssq = fmaf(x1, x1, ssq);
        ssq = fmaf(x2, x2, ssq);
        ssq = fmaf(x3, x3, ssq);
#pragma unroll
        for (int r = 0; r < 16; r++) {
            float4 wv = *(const float4*)&swm[(o0 + r) * 128 + c4];
            acc[r] += wv.x * x0 + wv.y * x1 + wv.z * x2 + wv.w * x3;
        }
    }
    float sp = rsqrtf(ssq * (1.f / 128.f) + EPSF);
#pragma unroll
    for (int r = 0; r < 16; r++)
        y[(o_base + o0 + r) * P + p] = fmaf(acc[r], sp, __ldg(&bias[o_base + o0 + r]));
}

// ======================= NATTEN attention ==================================
// Dilation 4 == upsample factor 4  =>  each query (i,j) attends to the
// contiguous 7x7 window starting at s0(i)=clamp((i-12)>>2,0,25) on the 32x32
// k-grid; constant across each 4x4 query tile. CTA = 8x8 queries = 2x2 tiles
// sharing one 8x8 key union (per-tile offset delta in {0,1}).
// 512 thr, 16 warps; warp = 4 queries of one tile (K/V smem reads amortized
// 4x across queries). grid (16,16).  [unchanged from passing round]
__global__ void __launch_bounds__(512) natten_k(const float* __restrict__ vin,
                                                float* __restrict__ out) {
    extern __shared__ float sm[];
    float* sq = sm;                      // 64 x 128 (reused as output staging)
    float* sk = sm + 8192;               // 64 keys x 132
    float* sv = sk + 64 * 132;           // 64 keys x 132
    float* sattn = sv + 64 * 132;        // 64 x 52

    const int t = threadIdx.x;
    const int w = t >> 5, lane = t & 31;
    const int j0 = blockIdx.x * 8, i0 = blockIdx.y * 8;

    int s0ai = (i0 - 12) >> 2; s0ai = max(0, min(25, s0ai));
    int s0bi = (i0 - 8) >> 2;  s0bi = max(0, min(25, s0bi));
    int s0aj = (j0 - 12) >> 2; s0aj = max(0, min(25, s0aj));
    int s0bj = (j0 - 8) >> 2;  s0bj = max(0, min(25, s0bj));

    // ---- stage q: 8x8 queries, sq[g][c] with g = qi*8 + qj ----
#pragma unroll
    for (int e = t; e < 2048; e += 512) {
        int c = e >> 4, rest = e & 15, qi = rest >> 1, half = rest & 1;
        float4 v4 = *(const float4*)&g_qp[c * 16384 + (i0 + qi) * 128 + j0 + 4 * half];
        int g0 = qi * 8 + 4 * half;
        sq[(g0 + 0) * 128 + c] = v4.x;
        sq[(g0 + 1) * 128 + c] = v4.y;
        sq[(g0 + 2) * 128 + c] = v4.z;
        sq[(g0 + 3) * 128 + c] = v4.w;
    }
    // ---- stage 8x8 key union (rows/cols clamped; clamped slots unread) ----
#pragma unroll
    for (int e = t; e < 8192; e += 512) {
        int c = e >> 6, kidx = e & 63, kr = kidx >> 3, kc = kidx & 7;
        int gr = min(s0ai + kr, 31), gc = min(s0aj + kc, 31);
        int ga = c * 1024 + gr * 32 + gc;
        sk[kidx * 132 + c] = g_kp[ga];
        sv[kidx * 132 + c] = vin[ga];
    }
    __syncthreads();

    // ---- warp -> tile T (0..3), 4 queries (one row of 4 within the tile) --
    const int T = w >> 2, ws = w & 3;
    const int di = (T >> 1) ? (s0bi - s0ai) : 0;
    const int dj = (T & 1) ? (s0bj - s0aj) : 0;
    const int gbase = (((T >> 1) << 2) + ws) * 8 + ((T & 1) << 2);

    const bool has2 = lane < 17;
    const int kk0 = lane, kk1 = has2 ? lane + 32 : lane;
    const float* k0p = &sk[((di + kk0 / 7) * 8 + dj + kk0 % 7) * 132];
    const float* k1p = &sk[((di + kk1 / 7) * 8 + dj + kk1 % 7) * 132];
    const float* qbase = &sq[gbase * 128];

    float attn0[4] = {0.f, 0.f, 0.f, 0.f}, attn1[4] = {0.f, 0.f, 0.f, 0.f};
#pragma unroll
    for (int h = 0; h < 4; h++) {
        float l0[4] = {0.f, 0.f, 0.f, 0.f}, l1[4] = {0.f, 0.f, 0.f, 0.f};
#pragma unroll
        for (int d4 = 0; d4 < 8; d4++) {
            int off = h * 32 + d4 * 4;
            float4 ka = *(const float4*)&k0p[off];
            float4 kb = *(const float4*)&k1p[off];
#pragma unroll
            for (int qq = 0; qq < 4; qq++) {
                float4 qd = *(const float4*)&qbase[qq * 128 + off];
                l0[qq] += qd.x * ka.x + qd.y * ka.y + qd.z * ka.z + qd.w * ka.w;
                l1[qq] += qd.x * kb.x + qd.y * kb.y + qd.z * kb.z + qd.w * kb.w;
            }
        }
        const float SC = 0.17677669529663687f;   // 32^-0.5
#pragma unroll
        for (int qq = 0; qq < 4; qq++) {
            float a0 = l0[qq] * SC, a1 = l1[qq] * SC;
            float mx = has2 ? fmaxf(a0, a1) : a0;
#pragma unroll
            for (int o = 16; o; o >>= 1)
                mx = fmaxf(mx, __shfl_xor_sync(0xffffffffu, mx, o));
            float e0 = __expf(a0 - mx);
            float e1 = has2 ? __expf(a1 - mx) : 0.f;
            float s = e0 + e1;
#pragma unroll
            for (int o = 16; o; o >>= 1)
                s += __shfl_xor_sync(0xffffffffu, s, o);
            float inv = 0.25f / s;               // fold mean over 4 heads
            attn0[qq] = fmaf(e0, inv, attn0[qq]);
            attn1[qq] = fmaf(e1, inv, attn1[qq]);
        }
    }
#pragma unroll
    for (int qq = 0; qq < 4; qq++) {
        sattn[(gbase + qq) * 52 + lane] = attn0[qq];
        if (has2) sattn[(gbase + qq) * 52 + lane + 32] = attn1[qq];
    }
    __syncwarp();

    // ---- AV: lane owns channels 4l..4l+3; V loaded once per key, used by
    // all 4 queries of the warp ----
    float4 a4[4];
#pragma unroll
    for (int qq = 0; qq < 4; qq++) a4[qq] = make_float4(0.f, 0.f, 0.f, 0.f);
#pragma unroll
    for (int m = 0; m < 7; m++) {
#pragma unroll
        for (int n = 0; n < 7; n++) {
            float4 vv = *(const float4*)&sv[((di + m) * 8 + dj + n) * 132 + 4 * lane];
            int kk = m * 7 + n;
#pragma unroll
            for (int qq = 0; qq < 4; qq++) {
                float aw = sattn[(gbase + qq) * 52 + kk];
                a4[qq].x = fmaf(aw, vv.x, a4[qq].x);
                a4[qq].y = fmaf(aw, vv.y, a4[qq].y);
                a4[qq].z = fmaf(aw, vv.z, a4[qq].z);
                a4[qq].w = fmaf(aw, vv.w, a4[qq].w);
            }
        }
    }
    // stage into sq (warp-private rows; no cross-warp hazard before barrier)
#pragma unroll
    for (int qq = 0; qq < 4; qq++)
        *(float4*)&sq[(gbase + qq) * 128 + 4 * lane] = a4[qq];
    __syncthreads();

    // ---- coalesced store: float4 along x per (c, qi, half) ----
#pragma unroll
    for (int e = t; e < 2048; e += 512) {
        int c = e >> 4, rest = e & 15, qi = rest >> 1, half = rest & 1;
        int g0 = qi * 8 + 4 * half;
        float4 o4 = make_float4(sq[(g0 + 0) * 128 + c], sq[(g0 + 1) * 128 + c],
                                sq[(g0 + 2) * 128 + c], sq[(g0 + 3) * 128 + c]);
        *(float4*)&out[c * 16384 + (i0 + qi) * 128 + j0 + 4 * half] = o4;
    }
}

// ============================== launch =====================================
extern "C" void kernel_launch(void* const* d_in, const int* in_sizes, int n_in,
                              void* d_out, int out_size) {
    const float* q  = (const float*)d_in[0];
    const float* k  = (const float*)d_in[1];
    const float* v  = (const float*)d_in[2];
    const float* cw = (const float*)d_in[3];
    const float* nq = (const float*)d_in[4];
    const float* nk = (const float*)d_in[5];
    const float* qw = (const float*)d_in[6];
    const float* qb = (const float*)d_in[7];
    const float* kw = (const float*)d_in[8];
    const float* kb = (const float*)d_in[9];
    float* out = (float*)d_out;

    // scratch addresses (cudaGetSymbolAddress is immediate, capture-safe)
    float *p_qc, *p_qp, *p_kp;
    cudaGetSymbolAddress((void**)&p_qc, g_qc);
    cudaGetSymbolAddress((void**)&p_qp, g_qp);
    cudaGetSymbolAddress((void**)&p_kp, g_kp);

    // opt-in smem limits (idempotent; deterministic)
    cudaFuncSetAttribute(proj_k, cudaFuncAttributeMaxDynamicSharedMemorySize,
                         64 * 128 * 4);
    const int natten_smem = (8192 + 2 * 64 * 132 + 64 * 52) * 4;  // 113664 B
    cudaFuncSetAttribute(natten_k, cudaFuncAttributeMaxDynamicSharedMemorySize,
                         natten_smem);

    // 1) 3x3 conv on q
    conv3x3_k<<<dim3(16, 16, 4), 256>>>(q, cw);
    // 2) fused rmsnorm + 1x1 projections (rms computed inline; o-split grid.y)
    proj_k<<<dim3(NPIX_Q / 64, 2), 256, 64 * 128 * 4>>>(p_qc, qw, qb, nq,
                                                        p_qp, NPIX_Q);
    proj_k<<<dim3(NPIX_K / 64, 2), 256, 64 * 128 * 4>>>(k, kw, kb, nk,
                                                        p_kp, NPIX_K);
    // 3) neighborhood attention + head-mean + AV
    natten_k<<<dim3(16, 16), 512, natten_smem>>>(v, out);
}